// round 4
// baseline (speedup 1.0000x reference)
#include <cuda_runtime.h>
#include <cstdint>

#define TM 32
#define THREADS 256

using ull = unsigned long long;

// ---- f32x2 packed math (Blackwell PTX-only path) ----
__device__ __forceinline__ ull pack2(float x) {
    ull r; unsigned u = __float_as_uint(x);
    asm("mov.b64 %0, {%1, %2};" : "=l"(r) : "r"(u), "r"(u));
    return r;
}
__device__ __forceinline__ ull fma2(ull a, ull b, ull c) {
    ull d;
    asm("fma.rn.f32x2 %0, %1, %2, %3;" : "=l"(d) : "l"(a), "l"(b), "l"(c));
    return d;
}
__device__ __forceinline__ void unpack2(ull v, float& lo, float& hi) {
    unsigned ulo, uhi;
    asm("mov.b64 {%0, %1}, %2;" : "=r"(ulo), "=r"(uhi) : "l"(v));
    lo = __uint_as_float(ulo); hi = __uint_as_float(uhi);
}

// ---- cp.async helpers ----
__device__ __forceinline__ void cp16(uint32_t dst, const void* src) {
    asm volatile("cp.async.cg.shared.global [%0], [%1], 16;" :: "r"(dst), "l"(src));
}
__device__ __forceinline__ void cp_commit() {
    asm volatile("cp.async.commit_group;");
}
template <int N> __device__ __forceinline__ void cp_wait() {
    asm volatile("cp.async.wait_group %0;" :: "n"(N));
}

// Shared layout (floats):
//  [0,     32768)  h0  (32x1024)   -- aliased by h2 (32x256) in layer2/3
//  [32768, 49152)  h1  (32x512)    -- aliased by W3+b3 stage in layer3
//  [49152, 57344)  w   (2 buffers x 4096 floats)
//  [57344, 57408)  coords (32x2)
#define SMEM_FLOATS 57408
#define SMEM_BYTES  (SMEM_FLOATS * 4)

__global__ void __launch_bounds__(THREADS, 1) ffn_kernel(
    const float* __restrict__ coord,
    const float* __restrict__ W0, const float* __restrict__ b0,
    const float* __restrict__ W1, const float* __restrict__ b1,
    const float* __restrict__ W2, const float* __restrict__ b2,
    const float* __restrict__ W3, const float* __restrict__ b3,
    float* __restrict__ out)
{
    extern __shared__ float sm[];
    float* sh0 = sm;            // h0 / h2
    float* sh1 = sm + 32768;    // h1 / W3 stage
    float* sw  = sm + 49152;    // weight tiles
    float* shc = sm + 57344;    // coords

    const int tid  = threadIdx.x;
    const int row0 = blockIdx.x * TM;

    const uint32_t sw_addr = (uint32_t)__cvta_generic_to_shared(sw);

    // ---------------- load coords ----------------
    if (tid < 64) shc[tid] = coord[row0 * 2 + tid];

    // Prefetch first two W1 tiles (8 rows x 512 = 4096 floats = 16KB each)
    {
        const float4* src = (const float4*)(W1);               // tile 0
        #pragma unroll
        for (int i = 0; i < 4; i++) {
            int e = tid + 256 * i;
            cp16(sw_addr + (uint32_t)(e * 16), src + e);
        }
        cp_commit();
        src = (const float4*)(W1 + 4096);                       // tile 1
        #pragma unroll
        for (int i = 0; i < 4; i++) {
            int e = tid + 256 * i;
            cp16(sw_addr + (uint32_t)(16384 + e * 16), src + e);
        }
        cp_commit();
    }

    __syncthreads();  // coords visible

    // ---------------- layer 0: h0 = relu(c @ W0 + b0) ----------------
    #pragma unroll
    for (int jt = 0; jt < 4; jt++) {
        int j = tid + 256 * jt;
        float w00 = W0[j], w01 = W0[1024 + j], bb = b0[j];
        #pragma unroll
        for (int m = 0; m < 32; m++) {
            float v = fmaf(shc[2 * m], w00, fmaf(shc[2 * m + 1], w01, bb));
            sh0[m * 1024 + j] = fmaxf(v, 0.0f);
        }
    }
    __syncthreads();

    // thread tiling for the GEMMs: 8 warps, warp = (m-group, n-half)
    const int wid = tid >> 5;
    const int tn  = tid & 31;
    const int m0  = (wid & 3) * 8;      // 8 rows per thread
    const int th  = wid >> 2;           // n half

    // ---------------- layer 1: h1 = relu(h0 @ W1 + b1)  [K=1024, N=512] ----
    {
        const int nb = th * 256 + 2 * tn;   // base column (pairs at +64*j)
        ull acc[8][4];
        #pragma unroll
        for (int r = 0; r < 8; r++)
            #pragma unroll
            for (int j = 0; j < 4; j++) acc[r][j] = 0ULL;

        for (int t = 0; t < 128; ++t) {
            if (t < 127) cp_wait<1>(); else cp_wait<0>();
            __syncthreads();

            const float* Wt = sw + ((t & 1) << 12);
            #pragma unroll
            for (int g = 0; g < 2; ++g) {
                float4 a4[8];
                #pragma unroll
                for (int r = 0; r < 8; ++r)
                    a4[r] = *(const float4*)&sh0[(m0 + r) * 1024 + t * 8 + g * 4];
                #pragma unroll
                for (int kk = 0; kk < 4; ++kk) {
                    const float* wrow = Wt + (g * 4 + kk) * 512 + nb;
                    ull w[4];
                    #pragma unroll
                    for (int j = 0; j < 4; ++j) w[j] = *(const ull*)(wrow + 64 * j);
                    #pragma unroll
                    for (int r = 0; r < 8; ++r) {
                        float av = (kk == 0) ? a4[r].x : (kk == 1) ? a4[r].y
                                 : (kk == 2) ? a4[r].z : a4[r].w;
                        ull a2 = pack2(av);
                        #pragma unroll
                        for (int j = 0; j < 4; ++j)
                            acc[r][j] = fma2(a2, w[j], acc[r][j]);
                    }
                }
            }
            __syncthreads();

            if (t + 2 < 128) {
                const float4* src = (const float4*)(W1 + (t + 2) * 4096);
                uint32_t base = sw_addr + (uint32_t)(((t + 2) & 1) * 16384);
                #pragma unroll
                for (int i = 0; i < 4; i++) {
                    int e = tid + 256 * i;
                    cp16(base + (uint32_t)(e * 16), src + e);
                }
                cp_commit();
            }
        }

        // epilogue: bias + relu -> sh1
        #pragma unroll
        for (int r = 0; r < 8; ++r) {
            #pragma unroll
            for (int j = 0; j < 4; ++j) {
                int col = nb + 64 * j;
                float lo, hi; unpack2(acc[r][j], lo, hi);
                float2 bb = *(const float2*)&b1[col];
                lo = fmaxf(lo + bb.x, 0.0f);
                hi = fmaxf(hi + bb.y, 0.0f);
                *(float2*)&sh1[(m0 + r) * 512 + col] = make_float2(lo, hi);
            }
        }
        __syncthreads();
    }

    // ---------------- layer 2: h2 = relu(h1 @ W2 + b2)  [K=512, N=256] ----
    {
        // prefetch first two W2 tiles (8 rows x 256 = 2048 floats = 8KB)
        {
            const float4* src = (const float4*)(W2);
            #pragma unroll
            for (int i = 0; i < 2; i++) {
                int e = tid + 256 * i;
                cp16(sw_addr + (uint32_t)(e * 16), src + e);
            }
            cp_commit();
            src = (const float4*)(W2 + 2048);
            #pragma unroll
            for (int i = 0; i < 2; i++) {
                int e = tid + 256 * i;
                cp16(sw_addr + (uint32_t)(16384 + e * 16), src + e);
            }
            cp_commit();
        }

        const int nb = th * 128 + 2 * tn;
        ull acc[8][2];
        #pragma unroll
        for (int r = 0; r < 8; r++) { acc[r][0] = 0ULL; acc[r][1] = 0ULL; }

        for (int t = 0; t < 64; ++t) {
            if (t < 63) cp_wait<1>(); else cp_wait<0>();
            __syncthreads();

            const float* Wt = sw + ((t & 1) << 12);
            #pragma unroll
            for (int g = 0; g < 2; ++g) {
                float4 a4[8];
                #pragma unroll
                for (int r = 0; r < 8; ++r)
                    a4[r] = *(const float4*)&sh1[(m0 + r) * 512 + t * 8 + g * 4];
                #pragma unroll
                for (int kk = 0; kk < 4; ++kk) {
                    const float* wrow = Wt + (g * 4 + kk) * 256 + nb;
                    ull w0v = *(const ull*)(wrow);
                    ull w1v = *(const ull*)(wrow + 64);
                    #pragma unroll
                    for (int r = 0; r < 8; ++r) {
                        float av = (kk == 0) ? a4[r].x : (kk == 1) ? a4[r].y
                                 : (kk == 2) ? a4[r].z : a4[r].w;
                        ull a2 = pack2(av);
                        acc[r][0] = fma2(a2, w0v, acc[r][0]);
                        acc[r][1] = fma2(a2, w1v, acc[r][1]);
                    }
                }
            }
            __syncthreads();

            if (t + 2 < 64) {
                const float4* src = (const float4*)(W2 + (t + 2) * 2048);
                uint32_t base = sw_addr + (uint32_t)(((t + 2) & 1) * 16384);
                #pragma unroll
                for (int i = 0; i < 2; i++) {
                    int e = tid + 256 * i;
                    cp16(base + (uint32_t)(e * 16), src + e);
                }
                cp_commit();
            }
        }

        // epilogue: bias + relu -> h2 (aliases sh0)
        #pragma unroll
        for (int r = 0; r < 8; ++r) {
            #pragma unroll
            for (int j = 0; j < 2; ++j) {
                int col = nb + 64 * j;
                float lo, hi; unpack2(acc[r][j], lo, hi);
                float2 bb = *(const float2*)&b2[col];
                lo = fmaxf(lo + bb.x, 0.0f);
                hi = fmaxf(hi + bb.y, 0.0f);
                *(float2*)&sh0[(m0 + r) * 256 + col] = make_float2(lo, hi);
            }
        }
        __syncthreads();
    }

    // ---------------- layer 3: out = h2 @ W3 + b3  [K=256, N=3] ----------
    // stage W3 (256x3 = 768 floats) + b3 into sh1 (free now).
    // NOTE: grid-stride — 768 > THREADS (this was the R2 correctness bug).
    for (int i = tid; i < 768; i += THREADS) sh1[i] = W3[i];
    if (tid < 3) sh1[768 + tid] = b3[tid];
    __syncthreads();

    if (tid < 96) {
        int m = tid / 3;
        int c = tid - m * 3;
        float acc = sh1[768 + c];
        #pragma unroll 8
        for (int k4 = 0; k4 < 64; ++k4) {
            float4 h = *(const float4*)&sh0[m * 256 + 4 * k4];
            acc = fmaf(h.x, sh1[(4 * k4 + 0) * 3 + c], acc);
            acc = fmaf(h.y, sh1[(4 * k4 + 1) * 3 + c], acc);
            acc = fmaf(h.z, sh1[(4 * k4 + 2) * 3 + c], acc);
            acc = fmaf(h.w, sh1[(4 * k4 + 3) * 3 + c], acc);
        }
        out[(row0 + m) * 3 + c] = acc;
    }
}

extern "C" void kernel_launch(void* const* d_in, const int* in_sizes, int n_in,
                              void* d_out, int out_size) {
    const float* coord = (const float*)d_in[0];
    const float* W0 = (const float*)d_in[1];
    const float* b0 = (const float*)d_in[2];
    const float* W1 = (const float*)d_in[3];
    const float* b1 = (const float*)d_in[4];
    const float* W2 = (const float*)d_in[5];
    const float* b2 = (const float*)d_in[6];
    const float* W3 = (const float*)d_in[7];
    const float* b3 = (const float*)d_in[8];
    float* out = (float*)d_out;

    int N = in_sizes[0] / 2;  // 262144
    int grid = N / TM;        // 8192

    cudaFuncSetAttribute(ffn_kernel,
                         cudaFuncAttributeMaxDynamicSharedMemorySize, SMEM_BYTES);
    ffn_kernel<<<grid, THREADS, SMEM_BYTES>>>(coord, W0, b0, W1, b1, W2, b2,
                                              W3, b3, out);
}